// round 1
// baseline (speedup 1.0000x reference)
#include <cuda_runtime.h>

#define ALPHA 100.0f
#define MG 5

static constexpr int B = 32, C = 3, H = 512, W = 512;
static constexpr int HW = H * W;
static constexpr int GROUPS = B * H * (W / 4);   // float4 groups per pixel-plane
static constexpr float INV_N = 1.0f / (float(B) * C * H * W);

__global__ void zero_out_kernel(float* out) { out[0] = 0.0f; }

__global__ void __launch_bounds__(256)
mae_bbox_kernel(const float* __restrict__ x,
                const float* __restrict__ y,
                const int*   __restrict__ bbox,
                float*       __restrict__ out)
{
    float acc = 0.0f;

    for (int g = blockIdx.x * blockDim.x + threadIdx.x; g < GROUPS;
         g += gridDim.x * blockDim.x)
    {
        const int b   = g >> 16;            // / (512*128)
        const int rem = g & 65535;
        const int h   = rem >> 7;           // row
        const int x0  = (rem & 127) << 2;   // first of 4 pixels

        // bbox[b]: 4 points, columns (x, y)
        const int* bb = bbox + b * 8;
        const int bx0 = bb[0], by0 = bb[1], bx1 = bb[2], by1 = bb[3];
        const int bx2 = bb[4], by2 = bb[5], bx3 = bb[6], by3 = bb[7];
        const int xmin = min(min(bx0, bx1), min(bx2, bx3));
        const int xmax = max(max(bx0, bx1), max(bx2, bx3));
        const int ymin = min(min(by0, by1), min(by2, by3));
        const int ymax = max(max(by0, by1), max(by2, by3));

        const bool cond = (xmin - MG > 0) && (xmax + MG < W) &&
                          (ymin - MG > 0) && (ymax + MG < H);

        const bool iny = (h >= ymin) && (h < ymax);
        const int fy = iny ? MG
                     : ((h >= ymin - MG && h < ymin) ? (h - ymin + MG + 1)
                     : ((h >= ymax && h < ymax + MG) ? (MG - (h - ymax)) : 0));

        float w[4];
        #pragma unroll
        for (int i = 0; i < 4; i++) {
            const int xp = x0 + i;
            const bool inx = (xp >= xmin) && (xp < xmax);
            const bool inside = inx && iny;
            const int fx = inx ? MG
                         : ((xp >= xmin - MG && xp < xmin) ? (xp - xmin + MG + 1)
                         : ((xp >= xmax && xp < xmax + MG) ? (MG - (xp - xmax)) : 0));
            float wi = inside ? ALPHA : 1.0f;
            if (cond && fy > 0 && fx > 0 && !inside)
                wi = (float)min(fy, fx) * (ALPHA / (float)MG);
            w[i] = wi;
        }

        const int base = b * C * HW + h * W + x0;
        #pragma unroll
        for (int c = 0; c < C; c++) {
            const float4 xv = *reinterpret_cast<const float4*>(x + base + c * HW);
            const float4 yv = *reinterpret_cast<const float4*>(y + base + c * HW);
            acc += fabsf(xv.x - yv.x) * w[0];
            acc += fabsf(xv.y - yv.y) * w[1];
            acc += fabsf(xv.z - yv.z) * w[2];
            acc += fabsf(xv.w - yv.w) * w[3];
        }
    }

    // warp reduce
    #pragma unroll
    for (int o = 16; o > 0; o >>= 1)
        acc += __shfl_down_sync(0xffffffff, acc, o);

    __shared__ float sm[8];
    const int lane = threadIdx.x & 31;
    const int wid  = threadIdx.x >> 5;
    if (lane == 0) sm[wid] = acc;
    __syncthreads();

    if (wid == 0) {
        acc = (lane < 8) ? sm[lane] : 0.0f;
        #pragma unroll
        for (int o = 4; o > 0; o >>= 1)
            acc += __shfl_down_sync(0xffffffff, acc, o);
        if (lane == 0)
            atomicAdd(out, acc * INV_N);
    }
}

extern "C" void kernel_launch(void* const* d_in, const int* in_sizes, int n_in,
                              void* d_out, int out_size)
{
    const float* x    = (const float*)d_in[0];
    const float* y    = (const float*)d_in[1];
    const int*   bbox = (const int*)d_in[2];
    float* out = (float*)d_out;

    zero_out_kernel<<<1, 1>>>(out);
    mae_bbox_kernel<<<1184, 256>>>(x, y, bbox, out);
}